// round 12
// baseline (speedup 1.0000x reference)
#include <cuda_runtime.h>

// ---------------------------------------------------------------------------
// StepWiseMLPAutoEncoder — fp32, packed fma.rn.f32x2
// decoder: persistent, 1024-thr blocks, 32-way k-split over padded K=1152
//          cat-buffer activations (ctrl copied in by spare blocks)
// ---------------------------------------------------------------------------

#define BATCH 64
#define SS    1024
#define TT    256
#define HH    64
#define EM    1056
#define DM    1056
#define KC    2048
#define KD1   1088
#define KV    1152                 // padded virtual K (32 * 36)
#define MROWS (BATCH*TT)
#define NBLK  132

typedef unsigned long long u64;

// scratch (device globals) — padded +256 floats for prefetch overshoot
__device__ float g_xT[BATCH * TT * SS];
__device__ float g_h1[(size_t)MROWS * EM];
__device__ float g_ctrlT[TT * HH * BATCH + 256];     // [T,H,B] k-major
__device__ float g_hdT[KV * BATCH + 256];            // [KV,B] (rows >=1056 zero)
__device__ float g_cat[2][KV * BATCH + 256];         // [KV,B]: ctrl|prev|pad
__device__ unsigned g_bar = 0;
__device__ unsigned g_gen = 0;

// ---- packed fp32x2 helpers -------------------------------------------------
__device__ __forceinline__ u64 pk2(float lo, float hi) {
    u64 r; asm("mov.b64 %0, {%1, %2};" : "=l"(r) : "f"(lo), "f"(hi)); return r;
}
__device__ __forceinline__ void fma2(u64& d, u64 a, u64 b) {
    asm("fma.rn.f32x2 %0, %1, %2, %0;" : "+l"(d) : "l"(a), "l"(b));
}
__device__ __forceinline__ void unpk2(u64 v, float& lo, float& hi) {
    asm("mov.b64 {%0, %1}, %2;" : "=f"(lo), "=f"(hi) : "l"(v));
}

// ---------------------------------------------------------------------------
__device__ __forceinline__ void grid_sync(int nb)
{
    __threadfence();
    __syncthreads();
    if (threadIdx.x == 0) {
        volatile unsigned* vgen = &g_gen;
        unsigned my = *vgen;
        if (atomicAdd(&g_bar, 1u) == (unsigned)(nb - 1)) {
            atomicExch(&g_bar, 0u);
            __threadfence();
            atomicExch(&g_gen, my + 1u);
        } else {
            while (*vgen == my) { }
            __threadfence();
        }
    }
    __syncthreads();
}

// ---------------------------------------------------------------------------
// x[b,s,t] -> xT[b,t,s]
// ---------------------------------------------------------------------------
__global__ void transpose_x_kernel(const float* __restrict__ x)
{
    __shared__ float tile[32][33];
    int b  = blockIdx.z;
    int t0 = blockIdx.x * 32;
    int s0 = blockIdx.y * 32;
    const float* xb  = x    + (size_t)b * SS * TT;
    float*       xTb = g_xT + (size_t)b * TT * SS;
    int tx = threadIdx.x, ty = threadIdx.y;
#pragma unroll
    for (int j = 0; j < 32; j += 8)
        tile[ty + j][tx] = xb[(s0 + ty + j) * TT + t0 + tx];
    __syncthreads();
#pragma unroll
    for (int j = 0; j < 32; j += 8)
        xTb[(t0 + ty + j) * SS + s0 + tx] = tile[tx][ty + j];
}

// ---------------------------------------------------------------------------
// enc0: h1 = relu(comb @ We1 + be1). 128x128 tile, BK=16, 256 threads, 8mx8n.
// ---------------------------------------------------------------------------
__global__ __launch_bounds__(256, 2) void enc0_kernel(
    const float* __restrict__ We1, const float* __restrict__ be1)
{
    __shared__ float As[16][132];
    __shared__ float Bs[16][128];

    int tid = threadIdx.x;
    int n0  = blockIdx.x * 128;
    int r0  = blockIdx.y * 128;
    int tm  = tid >> 4;
    int tn  = tid & 15;

    int arow[2], acol[2];
    const float* acur[2];
    const float* aprev[2];
#pragma unroll
    for (int it = 0; it < 2; it++) {
        int f = tid + it * 256;
        arow[it] = f >> 2;
        acol[it] = (f & 3) * 4;
        int r = r0 + arow[it];
        int b = r >> 8, t = r & 255;
        acur[it]  = g_xT + ((size_t)(b << 8) + t) * SS;
        aprev[it] = (t > 0) ? (acur[it] - SS) : nullptr;
    }
    int bk[2], bn[2];
#pragma unroll
    for (int it = 0; it < 2; it++) {
        int f = tid + it * 256;
        bk[it] = f >> 5;
        bn[it] = (f & 31) * 4;
    }

    u64 acc[8][4];
#pragma unroll
    for (int i = 0; i < 8; i++)
#pragma unroll
        for (int j = 0; j < 4; j++) acc[i][j] = 0ULL;

    float4 a_s[2], b_s[2];
#pragma unroll
    for (int it = 0; it < 2; it++) {
        int kg = acol[it];
        float4 v = make_float4(0.f, 0.f, 0.f, 0.f);
        if (kg < SS) { if (aprev[it]) v = *(const float4*)(aprev[it] + kg); }
        else           v = *(const float4*)(acur[it] + kg - SS);
        a_s[it] = v;
        int ng = n0 + bn[it];
        float4 w = make_float4(0.f, 0.f, 0.f, 0.f);
        if (ng < EM) w = *(const float4*)&We1[(size_t)bk[it] * EM + ng];
        b_s[it] = w;
    }

    for (int kc = 0; kc < KC; kc += 16) {
        __syncthreads();
#pragma unroll
        for (int it = 0; it < 2; it++) {
            As[acol[it] + 0][arow[it]] = a_s[it].x;
            As[acol[it] + 1][arow[it]] = a_s[it].y;
            As[acol[it] + 2][arow[it]] = a_s[it].z;
            As[acol[it] + 3][arow[it]] = a_s[it].w;
            *(float4*)&Bs[bk[it]][bn[it]] = b_s[it];
        }
        __syncthreads();

        if (kc + 16 < KC) {
#pragma unroll
            for (int it = 0; it < 2; it++) {
                int kg = kc + 16 + acol[it];
                float4 v = make_float4(0.f, 0.f, 0.f, 0.f);
                if (kg < SS) { if (aprev[it]) v = *(const float4*)(aprev[it] + kg); }
                else           v = *(const float4*)(acur[it] + kg - SS);
                a_s[it] = v;
                int ng = n0 + bn[it];
                float4 w = make_float4(0.f, 0.f, 0.f, 0.f);
                if (ng < EM) w = *(const float4*)&We1[(size_t)(kc + 16 + bk[it]) * EM + ng];
                b_s[it] = w;
            }
        }

#pragma unroll
        for (int kk = 0; kk < 16; kk++) {
            float4 a0 = *(const float4*)&As[kk][tm * 8];
            float4 a1 = *(const float4*)&As[kk][tm * 8 + 4];
            ulonglong2 w0 = *(const ulonglong2*)&Bs[kk][tn * 8];
            ulonglong2 w1 = *(const ulonglong2*)&Bs[kk][tn * 8 + 4];
            float am[8] = {a0.x, a0.y, a0.z, a0.w, a1.x, a1.y, a1.z, a1.w};
#pragma unroll
            for (int i = 0; i < 8; i++) {
                u64 ad = pk2(am[i], am[i]);
                fma2(acc[i][0], ad, w0.x);
                fma2(acc[i][1], ad, w0.y);
                fma2(acc[i][2], ad, w1.x);
                fma2(acc[i][3], ad, w1.y);
            }
        }
    }

#pragma unroll
    for (int i = 0; i < 8; i++) {
        float c[8];
        unpk2(acc[i][0], c[0], c[1]);
        unpk2(acc[i][1], c[2], c[3]);
        unpk2(acc[i][2], c[4], c[5]);
        unpk2(acc[i][3], c[6], c[7]);
        int rr = r0 + tm * 8 + i;
        float* dst = g_h1 + (size_t)rr * EM;
#pragma unroll
        for (int j = 0; j < 8; j++) {
            int ng = n0 + tn * 8 + j;
            if (ng < EM) dst[ng] = fmaxf(c[j] + be1[ng], 0.f);
        }
    }
}

// ---------------------------------------------------------------------------
// enc1: ctrl = h1 @ We2 + be2 -> g_ctrlT. 64x64 tile, 256 threads.
// ---------------------------------------------------------------------------
__global__ __launch_bounds__(256) void enc1_kernel(
    const float* __restrict__ Bmat, const float* __restrict__ bias)
{
    constexpr int N = HH;
    constexpr int K = EM;

    __shared__ float As[16][64];
    __shared__ float Bs[16][64];

    int tid  = threadIdx.x;
    int arow = tid >> 2;
    int acol = (tid & 3) * 4;
    int tn   = tid & 15;
    int tm   = tid >> 4;
    int r0   = blockIdx.y * 64;

    u64 acc2[4][2];
#pragma unroll
    for (int i = 0; i < 4; i++) { acc2[i][0] = 0ULL; acc2[i][1] = 0ULL; }

    const float* acur = g_h1 + (size_t)(r0 + arow) * K;

    for (int kc = 0; kc < K; kc += 16) {
        float4 av = *(const float4*)(acur + kc + acol);
        As[acol + 0][arow] = av.x;
        As[acol + 1][arow] = av.y;
        As[acol + 2][arow] = av.z;
        As[acol + 3][arow] = av.w;

#pragma unroll
        for (int it = 0; it < 4; it++) {
            int k = (tid >> 6) + it * 4;
            int n = tid & 63;
            float v = 0.f;
            if (n < N) v = Bmat[(size_t)(kc + k) * N + n];
            Bs[k][n] = v;
        }
        __syncthreads();

#pragma unroll
        for (int kk = 0; kk < 16; kk++) {
            float4 a4 = *(const float4*)&As[kk][tm * 4];
            ulonglong2 b2 = *(const ulonglong2*)&Bs[kk][tn * 4];
            u64 d0 = pk2(a4.x, a4.x);
            u64 d1 = pk2(a4.y, a4.y);
            u64 d2 = pk2(a4.z, a4.z);
            u64 d3 = pk2(a4.w, a4.w);
            fma2(acc2[0][0], d0, b2.x); fma2(acc2[0][1], d0, b2.y);
            fma2(acc2[1][0], d1, b2.x); fma2(acc2[1][1], d1, b2.y);
            fma2(acc2[2][0], d2, b2.x); fma2(acc2[2][1], d2, b2.y);
            fma2(acc2[3][0], d3, b2.x); fma2(acc2[3][1], d3, b2.y);
        }
        __syncthreads();
    }

#pragma unroll
    for (int i = 0; i < 4; i++) {
        float c[4];
        unpk2(acc2[i][0], c[0], c[1]);
        unpk2(acc2[i][1], c[2], c[3]);
        int rr = r0 + tm * 4 + i;
#pragma unroll
        for (int j = 0; j < 4; j++) {
            int ng = tn * 4 + j;
            if (ng < N) {
                float v = c[j] + bias[ng];
                int bb = rr >> 8;
                int tt = rr & 255;
                g_ctrlT[(tt * HH + ng) * BATCH + bb] = v;
            }
        }
    }
}

// ---------------------------------------------------------------------------
// Persistent decoder: 132 blocks x 1024 thr. Block = (nt=bid>>1, mh=bid&1):
// 16 n x 32 m. 32 warps = 32 uniform k-groups of 36 over padded KV=1152.
// Activations in cat-buffer [KV][64]: ctrl | prev | zero-pad.
// ---------------------------------------------------------------------------
#define DEC_SMEM ((KV*16*2 + 32*16*32) * 4)

__device__ __forceinline__ void dec_seg(
    u64 acc[8], const float* __restrict__ src, const float* __restrict__ Ws,
    int k0, int nk, int moff)
{
    const float* s = src + moff;
    const ulonglong2* wp = (const ulonglong2*)(Ws + k0 * 16);
    float av[4];
#pragma unroll
    for (int kk = 0; kk < 4; kk++) av[kk] = s[64 * kk];

    for (int i = 0; i < nk; i += 4) {
        s += 256;
        float nv[4];
#pragma unroll
        for (int kk = 0; kk < 4; kk++) nv[kk] = s[64 * kk];  // prefetch (padded)
#pragma unroll
        for (int kk = 0; kk < 4; kk++) {
            u64 ad = pk2(av[kk], av[kk]);
            ulonglong2 w0 = wp[0], w1 = wp[1], w2 = wp[2], w3 = wp[3];
            wp += 4;
            fma2(acc[0], ad, w0.x); fma2(acc[1], ad, w0.y);
            fma2(acc[2], ad, w1.x); fma2(acc[3], ad, w1.y);
            fma2(acc[4], ad, w2.x); fma2(acc[5], ad, w2.y);
            fma2(acc[6], ad, w3.x); fma2(acc[7], ad, w3.y);
        }
#pragma unroll
        for (int kk = 0; kk < 4; kk++) av[kk] = nv[kk];
    }
}

__global__ __launch_bounds__(1024, 1) void dec_persistent_kernel(
    const float* __restrict__ Wd1, const float* __restrict__ bd1,
    const float* __restrict__ Wd2, const float* __restrict__ bd2,
    float* __restrict__ out)
{
    extern __shared__ float sm[];
    float* Ws1 = sm;                        // [KV][16]
    float* Ws2 = sm + KV * 16;              // [KV][16]
    float* red = sm + KV * 32;              // [32g][16n][32m]

    int tid = threadIdx.x;
    int bid = blockIdx.x;
    int nt  = bid >> 1;          // n-tile 0..65
    int mh  = bid & 1;           // m-half
    int n0  = nt * 16;

    // weights: k-row-major [k][16], zero-padded to KV rows
    for (int i = tid; i < 16 * KV; i += 1024) {
        int k = i >> 4, n = i & 15;
        Ws1[i] = (k < KD1) ? Wd1[(size_t)k * DM + n0 + n] : 0.f;
    }
    if (nt < 64) {
        for (int i = tid; i < 16 * KV; i += 1024) {
            int k = i >> 4, n = i & 15;
            Ws2[i] = (k < DM) ? Wd2[(size_t)k * SS + n0 + n] : 0.f;
        }
    }
    // zero cat buffers + hdT pad (grid-strided)
    for (int i = bid * 1024 + tid; i < KV * BATCH + 256; i += NBLK * 1024) {
        g_cat[0][i] = 0.f;
        g_cat[1][i] = 0.f;
    }
    for (int i = bid * 1024 + tid; i < 96 * BATCH + 256; i += NBLK * 1024)
        g_hdT[1056 * BATCH + i] = 0.f;

    grid_sync(NBLK);

    // place ctrl_0 into cat[0] rows 0..63 (block nt==65 only)
    if (nt == 65) {
        for (int i = tid; i < HH * 32; i += 1024) {
            int r = i >> 5, c = i & 31;
            g_cat[0][r * 64 + mh * 32 + c] =
                g_ctrlT[((size_t)0 * HH + r) * BATCH + mh * 32 + c];
        }
    }

    int g    = tid >> 5;             // k-group 0..31
    int lane = tid & 31;
    int moff = mh * 32 + lane;
    int en   = (tid >> 5) & 15;      // epilogue n (tid<512)
    int em   = tid & 31;             // epilogue m

    float bv1 = bd1[n0 + en];
    float bv2 = (nt < 64) ? bd2[n0 + en] : 0.f;

    grid_sync(NBLK);

    for (int t = 0; t < TT; t++) {
        const float* cat = g_cat[t & 1];

        // ---- layer 1: hdT = relu(cat @ Ws1 + bd1)  (KV rows, 32 x 36)
        {
            u64 acc[8] = {};
            dec_seg(acc, cat + g * 36 * 64, Ws1, g * 36, 36, moff);
#pragma unroll
            for (int p = 0; p < 8; p++) {
                float lo, hi; unpk2(acc[p], lo, hi);
                red[(g * 16 + 2 * p) * 32 + lane]     = lo;
                red[(g * 16 + 2 * p + 1) * 32 + lane] = hi;
            }
            __syncthreads();

            if (tid < 512) {
                float v = bv1;
#pragma unroll
                for (int gg = 0; gg < 32; gg++)
                    v += red[(gg * 16 + en) * 32 + em];
                g_hdT[(n0 + en) * 64 + mh * 32 + em] = fmaxf(v, 0.f);
            }
        }
        grid_sync(NBLK);

        // ---- layer 2: out_t = hdT @ Ws2 + bd2  (KV rows, 32 x 36)
        if (nt < 64) {
            u64 acc[8] = {};
            dec_seg(acc, g_hdT + g * 36 * 64, Ws2, g * 36, 36, moff);
#pragma unroll
            for (int p = 0; p < 8; p++) {
                float lo, hi; unpk2(acc[p], lo, hi);
                red[(g * 16 + 2 * p) * 32 + lane]     = lo;
                red[(g * 16 + 2 * p + 1) * 32 + lane] = hi;
            }
            __syncthreads();

            if (tid < 512) {
                float v = bv2;
#pragma unroll
                for (int gg = 0; gg < 32; gg++)
                    v += red[(gg * 16 + en) * 32 + em];
                int s = n0 + en;
                int m = mh * 32 + em;
                g_cat[(t + 1) & 1][(64 + s) * 64 + m] = v;   // prev for t+1
                out[((size_t)m * SS + s) * TT + t] = v;
            }
        } else if (nt == 65 && t + 1 < TT) {
            // spare blocks: stage ctrl_{t+1} into next cat buffer
            for (int i = tid; i < HH * 32; i += 1024) {
                int r = i >> 5, c = i & 31;
                g_cat[(t + 1) & 1][r * 64 + mh * 32 + c] =
                    g_ctrlT[((size_t)(t + 1) * HH + r) * BATCH + mh * 32 + c];
            }
        }
        grid_sync(NBLK);
    }
}

// ---------------------------------------------------------------------------
extern "C" void kernel_launch(void* const* d_in, const int* in_sizes, int n_in,
                              void* d_out, int out_size)
{
    const float* x   = (const float*)d_in[0];
    const float* We1 = (const float*)d_in[1];
    const float* be1 = (const float*)d_in[2];
    const float* We2 = (const float*)d_in[3];
    const float* be2 = (const float*)d_in[4];
    const float* Wd1 = (const float*)d_in[5];
    const float* bd1 = (const float*)d_in[6];
    const float* Wd2 = (const float*)d_in[7];
    const float* bd2 = (const float*)d_in[8];
    float* out = (float*)d_out;

    cudaFuncSetAttribute(dec_persistent_kernel,
                         cudaFuncAttributeMaxDynamicSharedMemorySize, DEC_SMEM);

    transpose_x_kernel<<<dim3(TT / 32, SS / 32, BATCH), dim3(32, 8)>>>(x);
    enc0_kernel<<<dim3((EM + 127) / 128, MROWS / 128), 256>>>(We1, be1);
    enc1_kernel<<<dim3(1, MROWS / 64), 256>>>(We2, be2);

    dec_persistent_kernel<<<NBLK, 1024, DEC_SMEM>>>(Wd1, bd1, Wd2, bd2, out);
}

// round 14
// speedup vs baseline: 1.1662x; 1.1662x over previous
#include <cuda_runtime.h>

// ---------------------------------------------------------------------------
// StepWiseMLPAutoEncoder — fp32, packed fma.rn.f32x2
// decoder: persistent, 132 x 512thr, block = 8n x 64m (full batch),
//          thread = 2m x 8n  -> LDS:fma2 = 1:4 (crossbar de-bottlenecked)
// R13: fix layer-1 k-segmentation (16 x 68 = 1088; R12 dropped rows 1056-1087)
// ---------------------------------------------------------------------------

#define BATCH 64
#define SS    1024
#define TT    256
#define HH    64
#define EM    1056
#define DM    1056
#define KC    2048
#define KD1   1088
#define MROWS (BATCH*TT)
#define NBLK  132

typedef unsigned long long u64;

// scratch (device globals) — padded +256 floats for prefetch overshoot
__device__ float g_xT[BATCH * TT * SS];
__device__ float g_h1[(size_t)MROWS * EM];
__device__ float g_ctrlT[TT * HH * BATCH + 256];     // [T,H,B] k-major
__device__ float g_hdT[DM * BATCH + 256];            // [K,B]
__device__ float g_sbufT[2][SS * BATCH + 256];       // [S,B] ping-pong
__device__ unsigned g_bar = 0;
__device__ unsigned g_gen = 0;

// ---- packed fp32x2 helpers -------------------------------------------------
__device__ __forceinline__ u64 pk2(float lo, float hi) {
    u64 r; asm("mov.b64 %0, {%1, %2};" : "=l"(r) : "f"(lo), "f"(hi)); return r;
}
__device__ __forceinline__ void fma2(u64& d, u64 a, u64 b) {
    asm("fma.rn.f32x2 %0, %1, %2, %0;" : "+l"(d) : "l"(a), "l"(b));
}
__device__ __forceinline__ void unpk2(u64 v, float& lo, float& hi) {
    asm("mov.b64 {%0, %1}, %2;" : "=f"(lo), "=f"(hi) : "l"(v));
}

// ---------------------------------------------------------------------------
__device__ __forceinline__ void grid_sync(int nb)
{
    __threadfence();
    __syncthreads();
    if (threadIdx.x == 0) {
        volatile unsigned* vgen = &g_gen;
        unsigned my = *vgen;
        if (atomicAdd(&g_bar, 1u) == (unsigned)(nb - 1)) {
            atomicExch(&g_bar, 0u);
            __threadfence();
            atomicExch(&g_gen, my + 1u);
        } else {
            while (*vgen == my) { }
            __threadfence();
        }
    }
    __syncthreads();
}

// ---------------------------------------------------------------------------
// x[b,s,t] -> xT[b,t,s]
// ---------------------------------------------------------------------------
__global__ void transpose_x_kernel(const float* __restrict__ x)
{
    __shared__ float tile[32][33];
    int b  = blockIdx.z;
    int t0 = blockIdx.x * 32;
    int s0 = blockIdx.y * 32;
    const float* xb  = x    + (size_t)b * SS * TT;
    float*       xTb = g_xT + (size_t)b * TT * SS;
    int tx = threadIdx.x, ty = threadIdx.y;
#pragma unroll
    for (int j = 0; j < 32; j += 8)
        tile[ty + j][tx] = xb[(s0 + ty + j) * TT + t0 + tx];
    __syncthreads();
#pragma unroll
    for (int j = 0; j < 32; j += 8)
        xTb[(t0 + ty + j) * SS + s0 + tx] = tile[tx][ty + j];
}

// ---------------------------------------------------------------------------
// enc0: h1 = relu(comb @ We1 + be1). 128x128 tile, BK=16, 256 threads, 8mx8n.
// ---------------------------------------------------------------------------
__global__ __launch_bounds__(256, 2) void enc0_kernel(
    const float* __restrict__ We1, const float* __restrict__ be1)
{
    __shared__ float As[16][132];
    __shared__ float Bs[16][128];

    int tid = threadIdx.x;
    int n0  = blockIdx.x * 128;
    int r0  = blockIdx.y * 128;
    int tm  = tid >> 4;
    int tn  = tid & 15;

    int arow[2], acol[2];
    const float* acur[2];
    const float* aprev[2];
#pragma unroll
    for (int it = 0; it < 2; it++) {
        int f = tid + it * 256;
        arow[it] = f >> 2;
        acol[it] = (f & 3) * 4;
        int r = r0 + arow[it];
        int b = r >> 8, t = r & 255;
        acur[it]  = g_xT + ((size_t)(b << 8) + t) * SS;
        aprev[it] = (t > 0) ? (acur[it] - SS) : nullptr;
    }
    int bk[2], bn[2];
#pragma unroll
    for (int it = 0; it < 2; it++) {
        int f = tid + it * 256;
        bk[it] = f >> 5;
        bn[it] = (f & 31) * 4;
    }

    u64 acc[8][4];
#pragma unroll
    for (int i = 0; i < 8; i++)
#pragma unroll
        for (int j = 0; j < 4; j++) acc[i][j] = 0ULL;

    float4 a_s[2], b_s[2];
#pragma unroll
    for (int it = 0; it < 2; it++) {
        int kg = acol[it];
        float4 v = make_float4(0.f, 0.f, 0.f, 0.f);
        if (kg < SS) { if (aprev[it]) v = *(const float4*)(aprev[it] + kg); }
        else           v = *(const float4*)(acur[it] + kg - SS);
        a_s[it] = v;
        int ng = n0 + bn[it];
        float4 w = make_float4(0.f, 0.f, 0.f, 0.f);
        if (ng < EM) w = *(const float4*)&We1[(size_t)bk[it] * EM + ng];
        b_s[it] = w;
    }

    for (int kc = 0; kc < KC; kc += 16) {
        __syncthreads();
#pragma unroll
        for (int it = 0; it < 2; it++) {
            As[acol[it] + 0][arow[it]] = a_s[it].x;
            As[acol[it] + 1][arow[it]] = a_s[it].y;
            As[acol[it] + 2][arow[it]] = a_s[it].z;
            As[acol[it] + 3][arow[it]] = a_s[it].w;
            *(float4*)&Bs[bk[it]][bn[it]] = b_s[it];
        }
        __syncthreads();

        if (kc + 16 < KC) {
#pragma unroll
            for (int it = 0; it < 2; it++) {
                int kg = kc + 16 + acol[it];
                float4 v = make_float4(0.f, 0.f, 0.f, 0.f);
                if (kg < SS) { if (aprev[it]) v = *(const float4*)(aprev[it] + kg); }
                else           v = *(const float4*)(acur[it] + kg - SS);
                a_s[it] = v;
                int ng = n0 + bn[it];
                float4 w = make_float4(0.f, 0.f, 0.f, 0.f);
                if (ng < EM) w = *(const float4*)&We1[(size_t)(kc + 16 + bk[it]) * EM + ng];
                b_s[it] = w;
            }
        }

#pragma unroll
        for (int kk = 0; kk < 16; kk++) {
            float4 a0 = *(const float4*)&As[kk][tm * 8];
            float4 a1 = *(const float4*)&As[kk][tm * 8 + 4];
            ulonglong2 w0 = *(const ulonglong2*)&Bs[kk][tn * 8];
            ulonglong2 w1 = *(const ulonglong2*)&Bs[kk][tn * 8 + 4];
            float am[8] = {a0.x, a0.y, a0.z, a0.w, a1.x, a1.y, a1.z, a1.w};
#pragma unroll
            for (int i = 0; i < 8; i++) {
                u64 ad = pk2(am[i], am[i]);
                fma2(acc[i][0], ad, w0.x);
                fma2(acc[i][1], ad, w0.y);
                fma2(acc[i][2], ad, w1.x);
                fma2(acc[i][3], ad, w1.y);
            }
        }
    }

#pragma unroll
    for (int i = 0; i < 8; i++) {
        float c[8];
        unpk2(acc[i][0], c[0], c[1]);
        unpk2(acc[i][1], c[2], c[3]);
        unpk2(acc[i][2], c[4], c[5]);
        unpk2(acc[i][3], c[6], c[7]);
        int rr = r0 + tm * 8 + i;
        float* dst = g_h1 + (size_t)rr * EM;
#pragma unroll
        for (int j = 0; j < 8; j++) {
            int ng = n0 + tn * 8 + j;
            if (ng < EM) dst[ng] = fmaxf(c[j] + be1[ng], 0.f);
        }
    }
}

// ---------------------------------------------------------------------------
// enc1: ctrl = h1 @ We2 + be2 -> g_ctrlT. 64x64 tile, 256 threads.
// ---------------------------------------------------------------------------
__global__ __launch_bounds__(256) void enc1_kernel(
    const float* __restrict__ Bmat, const float* __restrict__ bias)
{
    constexpr int N = HH;
    constexpr int K = EM;

    __shared__ float As[16][64];
    __shared__ float Bs[16][64];

    int tid  = threadIdx.x;
    int arow = tid >> 2;
    int acol = (tid & 3) * 4;
    int tn   = tid & 15;
    int tm   = tid >> 4;
    int r0   = blockIdx.y * 64;

    u64 acc2[4][2];
#pragma unroll
    for (int i = 0; i < 4; i++) { acc2[i][0] = 0ULL; acc2[i][1] = 0ULL; }

    const float* acur = g_h1 + (size_t)(r0 + arow) * K;

    for (int kc = 0; kc < K; kc += 16) {
        float4 av = *(const float4*)(acur + kc + acol);
        As[acol + 0][arow] = av.x;
        As[acol + 1][arow] = av.y;
        As[acol + 2][arow] = av.z;
        As[acol + 3][arow] = av.w;

#pragma unroll
        for (int it = 0; it < 4; it++) {
            int k = (tid >> 6) + it * 4;
            int n = tid & 63;
            float v = 0.f;
            if (n < N) v = Bmat[(size_t)(kc + k) * N + n];
            Bs[k][n] = v;
        }
        __syncthreads();

#pragma unroll
        for (int kk = 0; kk < 16; kk++) {
            float4 a4 = *(const float4*)&As[kk][tm * 4];
            ulonglong2 b2 = *(const ulonglong2*)&Bs[kk][tn * 4];
            u64 d0 = pk2(a4.x, a4.x);
            u64 d1 = pk2(a4.y, a4.y);
            u64 d2 = pk2(a4.z, a4.z);
            u64 d3 = pk2(a4.w, a4.w);
            fma2(acc2[0][0], d0, b2.x); fma2(acc2[0][1], d0, b2.y);
            fma2(acc2[1][0], d1, b2.x); fma2(acc2[1][1], d1, b2.y);
            fma2(acc2[2][0], d2, b2.x); fma2(acc2[2][1], d2, b2.y);
            fma2(acc2[3][0], d3, b2.x); fma2(acc2[3][1], d3, b2.y);
        }
        __syncthreads();
    }

#pragma unroll
    for (int i = 0; i < 4; i++) {
        float c[4];
        unpk2(acc2[i][0], c[0], c[1]);
        unpk2(acc2[i][1], c[2], c[3]);
        int rr = r0 + tm * 4 + i;
#pragma unroll
        for (int j = 0; j < 4; j++) {
            int ng = tn * 4 + j;
            if (ng < N) {
                float v = c[j] + bias[ng];
                int bb = rr >> 8;
                int tt = rr & 255;
                g_ctrlT[(tt * HH + ng) * BATCH + bb] = v;
            }
        }
    }
}

// ---------------------------------------------------------------------------
// Persistent decoder: 132 blocks x 512 thr. Block = n-tile (8 cols) x 64 m.
// 16 warps = 16 k-split groups. Thread: m = {2*lane, 2*lane+1}, 8 n
// (acc[0..3] = m0 n-pairs, acc[4..7] = m1 n-pairs).
// Per k per warp: 1 LDG.64 + 2 LDS.128 + 8 fma2  (LDS:fma2 = 1:4).
// ---------------------------------------------------------------------------
#define DEC_SMEM ((KD1*8 + DM*8 + 16*8*64) * 4)

__device__ __forceinline__ void dec_seg2(
    u64 acc[8], const float* __restrict__ src, const float* __restrict__ Ws,
    int k0, int nk, int mo)
{
    const float2* s = (const float2*)(src + mo);        // mo = 2*lane (8B align)
    const ulonglong2* wp = (const ulonglong2*)(Ws + k0 * 8);
    float2 av[4];
#pragma unroll
    for (int kk = 0; kk < 4; kk++) av[kk] = s[32 * kk];

    for (int i = 0; i < nk; i += 4) {
        s += 128;                                        // 4 k rows ahead
        float2 nv[4];
#pragma unroll
        for (int kk = 0; kk < 4; kk++) nv[kk] = s[32 * kk];  // prefetch (padded)
#pragma unroll
        for (int kk = 0; kk < 4; kk++) {
            u64 a0 = pk2(av[kk].x, av[kk].x);
            u64 a1 = pk2(av[kk].y, av[kk].y);
            ulonglong2 w0 = wp[0], w1 = wp[1];
            wp += 2;
            fma2(acc[0], a0, w0.x); fma2(acc[1], a0, w0.y);
            fma2(acc[2], a0, w1.x); fma2(acc[3], a0, w1.y);
            fma2(acc[4], a1, w0.x); fma2(acc[5], a1, w0.y);
            fma2(acc[6], a1, w1.x); fma2(acc[7], a1, w1.y);
        }
#pragma unroll
        for (int kk = 0; kk < 4; kk++) av[kk] = nv[kk];
    }
}

__global__ __launch_bounds__(512) void dec_persistent_kernel(
    const float* __restrict__ Wd1, const float* __restrict__ bd1,
    const float* __restrict__ Wd2, const float* __restrict__ bd2,
    float* __restrict__ out)
{
    extern __shared__ float sm[];
    float* Ws1 = sm;                        // [KD1][8]
    float* Ws2 = sm + KD1 * 8;              // [DM][8]
    float* red = sm + (KD1 + DM) * 8;       // [16g][8n][64m]

    int tid = threadIdx.x;
    int bid = blockIdx.x;                   // n-tile 0..131
    int n0  = bid * 8;

    // one-time weight cache, k-row-major [k][8]
    for (int i = tid; i < 8 * KD1; i += 512) {
        int k = i >> 3, n = i & 7;
        Ws1[i] = Wd1[(size_t)k * DM + n0 + n];
    }
    if (bid < 128) {
        for (int i = tid; i < 8 * DM; i += 512) {
            int k = i >> 3, n = i & 7;
            Ws2[i] = Wd2[(size_t)k * SS + n0 + n];
        }
    }
    // zero initial prev buffer
    for (int i = bid * 512 + tid; i < SS * BATCH; i += NBLK * 512)
        g_sbufT[0][i] = 0.f;

    int g    = tid >> 5;             // k-split group 0..15
    int lane = tid & 31;
    int mo   = lane * 2;             // thread m-pair base
    int en   = tid >> 6;             // epilogue n 0..7
    int em   = tid & 63;             // epilogue m 0..63

    float bv1 = bd1[n0 + en];
    float bv2 = (bid < 128) ? bd2[n0 + en] : 0.f;

    // layer1: 16 x 68 = 1088 exactly (g0: 64 ctrl + 4 prev)
    int kb1 = g * 68;
    // layer2: 8 x 68 + 8 x 64 = 1056 exactly
    int kb2 = (g < 8) ? g * 68 : 544 + (g - 8) * 64;
    int nk2 = (g < 8) ? 68 : 64;

    grid_sync(NBLK);

    for (int t = 0; t < TT; t++) {
        const float* sbT = g_sbufT[t & 1];
        const float* ctrl_base = g_ctrlT + t * HH * BATCH;

        // ---- layer 1: hdT = relu([ctrl_t | prev] @ Wd1 + bd1), K=1088
        {
            u64 acc[8] = {};
            if (g == 0) {
                dec_seg2(acc, ctrl_base, Ws1, 0, 64, mo);    // k 0..63 (ctrl)
                dec_seg2(acc, sbT, Ws1, 64, 4, mo);          // k 64..67
            } else {
                dec_seg2(acc, sbT + (kb1 - HH) * 64, Ws1, kb1, 68, mo);
            }
#pragma unroll
            for (int p = 0; p < 4; p++) {
                float l0, h0, l1, h1;
                unpk2(acc[p],     l0, h0);   // m0: n=2p, 2p+1
                unpk2(acc[4 + p], l1, h1);   // m1
                red[(g * 8 + 2 * p)     * 64 + mo]     = l0;
                red[(g * 8 + 2 * p + 1) * 64 + mo]     = h0;
                red[(g * 8 + 2 * p)     * 64 + mo + 1] = l1;
                red[(g * 8 + 2 * p + 1) * 64 + mo + 1] = h1;
            }
            __syncthreads();

            float v = bv1;
#pragma unroll
            for (int gg = 0; gg < 16; gg++)
                v += red[(gg * 8 + en) * 64 + em];
            g_hdT[(n0 + en) * 64 + em] = fmaxf(v, 0.f);
        }
        grid_sync(NBLK);

        // ---- layer 2: out_t = hdT @ Wd2 + bd2, K=1056
        if (bid < 128) {
            u64 acc[8] = {};
            dec_seg2(acc, g_hdT + kb2 * 64, Ws2, kb2, nk2, mo);
#pragma unroll
            for (int p = 0; p < 4; p++) {
                float l0, h0, l1, h1;
                unpk2(acc[p],     l0, h0);
                unpk2(acc[4 + p], l1, h1);
                red[(g * 8 + 2 * p)     * 64 + mo]     = l0;
                red[(g * 8 + 2 * p + 1) * 64 + mo]     = h0;
                red[(g * 8 + 2 * p)     * 64 + mo + 1] = l1;
                red[(g * 8 + 2 * p + 1) * 64 + mo + 1] = h1;
            }
            __syncthreads();

            float v = bv2;
#pragma unroll
            for (int gg = 0; gg < 16; gg++)
                v += red[(gg * 8 + en) * 64 + em];
            int s = n0 + en;
            g_sbufT[(t + 1) & 1][s * 64 + em] = v;
            out[((size_t)em * SS + s) * TT + t] = v;
        }
        grid_sync(NBLK);
    }
}

// ---------------------------------------------------------------------------
extern "C" void kernel_launch(void* const* d_in, const int* in_sizes, int n_in,
                              void* d_out, int out_size)
{
    const float* x   = (const float*)d_in[0];
    const float* We1 = (const float*)d_in[1];
    const float* be1 = (const float*)d_in[2];
    const float* We2 = (const float*)d_in[3];
    const float* be2 = (const float*)d_in[4];
    const float* Wd1 = (const float*)d_in[5];
    const float* bd1 = (const float*)d_in[6];
    const float* Wd2 = (const float*)d_in[7];
    const float* bd2 = (const float*)d_in[8];
    float* out = (float*)d_out;

    cudaFuncSetAttribute(dec_persistent_kernel,
                         cudaFuncAttributeMaxDynamicSharedMemorySize, DEC_SMEM);

    transpose_x_kernel<<<dim3(TT / 32, SS / 32, BATCH), dim3(32, 8)>>>(x);
    enc0_kernel<<<dim3((EM + 127) / 128, MROWS / 128), 256>>>(We1, be1);
    enc1_kernel<<<dim3(1, MROWS / 64), 256>>>(We2, be2);

    dec_persistent_kernel<<<NBLK, 512, DEC_SMEM>>>(Wd1, bd1, Wd2, bd2, out);
}